// round 11
// baseline (speedup 1.0000x reference)
#include <cuda_runtime.h>
#include <cuda_fp16.h>
#include <math.h>
#include <stdint.h>

// ---------------------------------------------------------------------------
// Problem constants
// ---------------------------------------------------------------------------
#define B_  4
#define L_  384
#define H_  128
#define F_  384
#define M1_ (B_ * L_ * L_)      // 589824 edge rows

// ---------------------------------------------------------------------------
// Device scratch (allocation-free rule)
// ---------------------------------------------------------------------------
__device__ __half g_hEh[(size_t)M1_ * H_];      // fp16 copy of h_E
__device__ __half g_T1h[(size_t)M1_ * F_];      // fp16 gelu(h_E @ fw1 + fb1)
__device__ float  g_xconv[(size_t)B_ * L_ * F_];
__device__ float  g_predm[B_ * L_];
__device__ __half g_fw1T[F_ * H_];              // [n=384][k=128] fp16
__device__ __half g_fw2T[F_ * F_];              // [n=384][k=384] fp16

__device__ __forceinline__ float gelu_f(float x) {
    return 0.5f * x * (1.0f + erff(x * 0.70710678118654752440f));
}

__device__ __forceinline__ uint32_t smem_u32(const void* p) {
    uint32_t a;
    asm("{ .reg .u64 t; cvta.to.shared.u64 t, %1; cvt.u32.u64 %0, t; }" : "=r"(a) : "l"(p));
    return a;
}

// m16n8k16 fp16 MMA, fp32 accumulate.
__device__ __forceinline__ void mma16(float* c, const uint32_t* a, uint32_t b0, uint32_t b1) {
    asm volatile(
        "mma.sync.aligned.m16n8k16.row.col.f32.f16.f16.f32 "
        "{%0,%1,%2,%3}, {%4,%5,%6,%7}, {%8,%9}, {%0,%1,%2,%3};"
        : "+f"(c[0]), "+f"(c[1]), "+f"(c[2]), "+f"(c[3])
        : "r"(a[0]), "r"(a[1]), "r"(a[2]), "r"(a[3]), "r"(b0), "r"(b1));
}

__device__ __forceinline__ void ldsm4(uint32_t& r0, uint32_t& r1, uint32_t& r2,
                                      uint32_t& r3, uint32_t addr) {
    asm volatile("ldmatrix.sync.aligned.m8n8.x4.shared.b16 {%0,%1,%2,%3}, [%4];"
                 : "=r"(r0), "=r"(r1), "=r"(r2), "=r"(r3) : "r"(addr));
}

__device__ __forceinline__ void ldsm2(uint32_t& r0, uint32_t& r1, uint32_t addr) {
    asm volatile("ldmatrix.sync.aligned.m8n8.x2.shared.b16 {%0,%1}, [%2];"
                 : "=r"(r0), "=r"(r1) : "r"(addr));
}

#define CP_COMMIT() asm volatile("cp.async.commit_group;" ::: "memory")
#define CP_WAIT1()  asm volatile("cp.async.wait_group 1;" ::: "memory")
#define CP_WAIT0()  asm volatile("cp.async.wait_group 0;" ::: "memory")

// Stage [128 rows x 32 half] (row stride ldg halves), row pitch 80 B.
__device__ __forceinline__ void stage128(const __half* __restrict__ g, int ldg,
                                         uint32_t s_addr, int tid) {
#pragma unroll
    for (int i = 0; i < 2; ++i) {
        int idx = tid + i * 256;
        int row = idx >> 2, q = idx & 3;
        uint32_t dst = s_addr + (uint32_t)(row * 80 + q * 16);
        const __half* src = g + (size_t)row * ldg + q * 8;
        asm volatile("cp.async.cg.shared.global [%0], [%1], 16;" :: "r"(dst), "l"(src));
    }
}

// Stage [64 rows x 32 half]
__device__ __forceinline__ void stage64(const __half* __restrict__ g, int ldg,
                                        uint32_t s_addr, int tid) {
    int row = tid >> 2, q = tid & 3;
    uint32_t dst = s_addr + (uint32_t)(row * 80 + q * 16);
    const __half* src = g + (size_t)row * ldg + q * 8;
    asm volatile("cp.async.cg.shared.global [%0], [%1], 16;" :: "r"(dst), "l"(src));
}

// ---------------------------------------------------------------------------
// Dynamic smem layout (bytes): 3-stage A (128x40h) + 3-stage B (64x40h)
// ---------------------------------------------------------------------------
#define SA_   10240
#define SBB_  5120
#define O_A   0                      // 3 x SA_
#define O_B   (3 * SA_)              // 3 x SBB_
#define O_BIAS (O_B + 3 * SBB_)      // 64 floats
#define O_RED  (O_BIAS + 256)        // 4 x 64 floats (gemm2)
#define O_XACC (O_RED + 1024)        // 64 floats (gemm2)
#define SMEM1  (O_BIAS + 256)
#define SMEM2  (O_XACC + 256)

// ---------------------------------------------------------------------------
// Kernel 0a: convert h_E (fp32) -> fp16
// ---------------------------------------------------------------------------
__global__ void __launch_bounds__(256) conv_hE(const float* __restrict__ hE) {
    size_t i = ((size_t)blockIdx.x * 256 + threadIdx.x) * 4;
    float4 v = *reinterpret_cast<const float4*>(hE + i);
    *reinterpret_cast<__half2*>(g_hEh + i)     = __floats2half2_rn(v.x, v.y);
    *reinterpret_cast<__half2*>(g_hEh + i + 2) = __floats2half2_rn(v.z, v.w);
}

// ---------------------------------------------------------------------------
// Kernel 0b: transpose weights to [n][k] fp16
// ---------------------------------------------------------------------------
__global__ void __launch_bounds__(256) transpose_w(const float* __restrict__ fw1,
                                                   const float* __restrict__ fw2) {
    int idx = blockIdx.x * 256 + threadIdx.x;
    if (idx < F_ * H_) {
        int n = idx / H_, k = idx % H_;
        g_fw1T[idx] = __float2half_rn(fw1[k * F_ + n]);
    }
    int i2 = idx - F_ * H_;
    if (i2 >= 0 && i2 < F_ * F_) {
        int n = i2 / F_, k = i2 % F_;
        g_fw2T[i2] = __float2half_rn(fw2[k * F_ + n]);
    }
}

// ---------------------------------------------------------------------------
// Warp MMA over one K=32 chunk. Warp tile 32(m) x 32(n).
// acc[2][4][4]; A via ldmatrix.x4 (16m x 16k), B via ldmatrix.x2 (8n x 16k).
// ---------------------------------------------------------------------------
__device__ __forceinline__ void mma_chunk(uint32_t aA, uint32_t aB,
                                          float acc[2][4][4],
                                          uint32_t aoffA, uint32_t aoffB) {
#pragma unroll
    for (int ks = 0; ks < 2; ++ks) {
        uint32_t af[2][4];
#pragma unroll
        for (int mt = 0; mt < 2; ++mt)
            ldsm4(af[mt][0], af[mt][1], af[mt][2], af[mt][3],
                  aA + aoffA + mt * 1280 + ks * 32);
        uint32_t bf[4][2];
#pragma unroll
        for (int nt = 0; nt < 4; ++nt)
            ldsm2(bf[nt][0], bf[nt][1], aB + aoffB + nt * 640 + ks * 32);
#pragma unroll
        for (int mt = 0; mt < 2; ++mt)
#pragma unroll
            for (int nt = 0; nt < 4; ++nt)
                mma16(acc[mt][nt], af[mt], bf[nt][0], bf[nt][1]);
    }
}

// ---------------------------------------------------------------------------
// Kernel 1: T1 = fp16(gelu(h_E @ fw1 + fb1))
//   grid (6, 4608): CTA tile 128(m) x 64(n); 8 warps = 4(wm) x 2(wn),
//   warp tile 32x32. K=128 in 4 chunks; 3-stage cp.async, 1 sync/chunk.
// ---------------------------------------------------------------------------
__global__ void __launch_bounds__(256, 4) gemm1_mma(const float* __restrict__ fb1) {
    extern __shared__ char smc[];
    const uint32_t sb = smem_u32(smc);
    float* biasS = reinterpret_cast<float*>(smc + O_BIAS);

    const int tid = threadIdx.x;
    const int wid = tid >> 5, lane = tid & 31;
    const int gid = lane >> 2, tig = lane & 3;
    const int g8 = lane >> 3, lr = lane & 7;
    const int wm = wid & 3, wn = wid >> 2;
    const int m0 = blockIdx.y * 128, n0 = blockIdx.x * 64;

    const uint32_t aoffA = (uint32_t)((wm * 32 + (g8 & 1) * 8 + lr) * 80 + (g8 >> 1) * 16);
    const uint32_t aoffB = (uint32_t)((wn * 32 + lr) * 80 + (g8 & 1) * 16);

    if (tid < 64) biasS[tid] = fb1[n0 + tid];

    float acc[2][4][4];
#pragma unroll
    for (int mt = 0; mt < 2; ++mt)
#pragma unroll
        for (int nt = 0; nt < 4; ++nt)
#pragma unroll
            for (int j = 0; j < 4; ++j) acc[mt][nt][j] = 0.f;

    const __half* Abase = g_hEh + (size_t)m0 * H_;
    const __half* Bbase = g_fw1T + (size_t)n0 * H_;

    stage128(Abase, H_, sb + O_A, tid);
    stage64(Bbase, H_, sb + O_B, tid);
    CP_COMMIT();
    stage128(Abase + 32, H_, sb + O_A + SA_, tid);
    stage64(Bbase + 32, H_, sb + O_B + SBB_, tid);
    CP_COMMIT();

#pragma unroll
    for (int kc = 0; kc < 4; ++kc) {
        const int cur = kc % 3;
        if (kc + 1 < 4) { CP_WAIT1(); } else { CP_WAIT0(); }
        __syncthreads();
        if (kc + 2 < 4) {
            const int nxt = (kc + 2) % 3;
            stage128(Abase + (kc + 2) * 32, H_, sb + O_A + nxt * SA_, tid);
            stage64(Bbase + (kc + 2) * 32, H_, sb + O_B + nxt * SBB_, tid);
            CP_COMMIT();
        }
        mma_chunk(sb + O_A + cur * SA_, sb + O_B + cur * SBB_, acc, aoffA, aoffB);
    }

    // Epilogue: bias + exact-erf gelu, fp16 half2 stores
#pragma unroll
    for (int mt = 0; mt < 2; ++mt)
#pragma unroll
        for (int nt = 0; nt < 4; ++nt) {
            float* c = acc[mt][nt];
            int lrr = wm * 32 + mt * 16 + gid;
            int lc = wn * 32 + nt * 8 + 2 * tig;
            float b0v = biasS[lc], b1v = biasS[lc + 1];
            size_t base = (size_t)(m0 + lrr) * F_ + n0 + lc;
            *reinterpret_cast<__half2*>(g_T1h + base) =
                __floats2half2_rn(gelu_f(c[0] + b0v), gelu_f(c[1] + b1v));
            *reinterpret_cast<__half2*>(g_T1h + base + (size_t)8 * F_) =
                __floats2half2_rn(gelu_f(c[2] + b0v), gelu_f(c[3] + b1v));
        }
}

// ---------------------------------------------------------------------------
// Kernel 2: per (bl, n-tile 64): T2 = gelu(T1_bl @ fw2 + fb2);
//           xconv[bl, n] = sum_k hV[b,k,n] * T2[k,n]
//   grid (6, 1536). 3 m-tiles of 128 k-edges, K=384 in 12 chunks, 3-stage.
// ---------------------------------------------------------------------------
__global__ void __launch_bounds__(256, 4) gemm2_mma(const float* __restrict__ hV,
                                                    const float* __restrict__ fb2) {
    extern __shared__ char smc[];
    const uint32_t sb = smem_u32(smc);
    float* biasS = reinterpret_cast<float*>(smc + O_BIAS);
    float (*red)[64] = reinterpret_cast<float (*)[64]>(smc + O_RED);
    float* xacc = reinterpret_cast<float*>(smc + O_XACC);

    const int tid = threadIdx.x;
    const int wid = tid >> 5, lane = tid & 31;
    const int gid = lane >> 2, tig = lane & 3;
    const int g8 = lane >> 3, lr = lane & 7;
    const int wm = wid & 3, wn = wid >> 2;
    const int bl = blockIdx.y, b = bl / L_;
    const int n0 = blockIdx.x * 64;

    const uint32_t aoffA = (uint32_t)((wm * 32 + (g8 & 1) * 8 + lr) * 80 + (g8 >> 1) * 16);
    const uint32_t aoffB = (uint32_t)((wn * 32 + lr) * 80 + (g8 & 1) * 16);

    if (tid < 64) { biasS[tid] = fb2[n0 + tid]; xacc[tid] = 0.f; }

    const __half* Bbase = g_fw2T + (size_t)n0 * F_;

    for (int mt = 0; mt < 3; ++mt) {
        float acc[2][4][4];
#pragma unroll
        for (int m2 = 0; m2 < 2; ++m2)
#pragma unroll
            for (int nt = 0; nt < 4; ++nt)
#pragma unroll
                for (int j = 0; j < 4; ++j) acc[m2][nt][j] = 0.f;

        const __half* Abase = g_T1h + (size_t)(bl * L_ + mt * 128) * F_;

        stage128(Abase, F_, sb + O_A, tid);
        stage64(Bbase, F_, sb + O_B, tid);
        CP_COMMIT();
        stage128(Abase + 32, F_, sb + O_A + SA_, tid);
        stage64(Bbase + 32, F_, sb + O_B + SBB_, tid);
        CP_COMMIT();

        for (int kc = 0; kc < 12; ++kc) {
            const int cur = kc % 3;
            if (kc + 1 < 12) { CP_WAIT1(); } else { CP_WAIT0(); }
            __syncthreads();
            if (kc + 2 < 12) {
                const int nxt = (kc + 2) % 3;
                stage128(Abase + (kc + 2) * 32, F_, sb + O_A + nxt * SA_, tid);
                stage64(Bbase + (kc + 2) * 32, F_, sb + O_B + nxt * SBB_, tid);
                CP_COMMIT();
            }
            mma_chunk(sb + O_A + cur * SA_, sb + O_B + cur * SBB_, acc, aoffA, aoffB);
        }

        // Fused epilogue: gelu + bias, * hV, reduce over 128 k-edge rows
        float p0[4], p1[4];
#pragma unroll
        for (int nt = 0; nt < 4; ++nt) { p0[nt] = 0.f; p1[nt] = 0.f; }

#pragma unroll
        for (int m2 = 0; m2 < 2; ++m2)
#pragma unroll
            for (int nt = 0; nt < 4; ++nt) {
                float* c = acc[m2][nt];
                int r0 = wm * 32 + m2 * 16 + gid;
                int lc = wn * 32 + nt * 8 + 2 * tig;
                float b0v = biasS[lc], b1v = biasS[lc + 1];
                const float* hv0 = hV + ((size_t)b * L_ + mt * 128 + r0) * F_ + n0 + lc;
                float2 h0 = *reinterpret_cast<const float2*>(hv0);
                float2 h1 = *reinterpret_cast<const float2*>(hv0 + (size_t)8 * F_);
                p0[nt] += gelu_f(c[0] + b0v) * h0.x + gelu_f(c[2] + b0v) * h1.x;
                p1[nt] += gelu_f(c[1] + b1v) * h0.y + gelu_f(c[3] + b1v) * h1.y;
            }

        // butterfly over gid (lane bits 2..4)
#pragma unroll
        for (int nt = 0; nt < 4; ++nt) {
#pragma unroll
            for (int off = 16; off >= 4; off >>= 1) {
                p0[nt] += __shfl_xor_sync(0xFFFFFFFFu, p0[nt], off);
                p1[nt] += __shfl_xor_sync(0xFFFFFFFFu, p1[nt], off);
            }
        }
        if (gid == 0) {
#pragma unroll
            for (int nt = 0; nt < 4; ++nt) {
                red[wm][wn * 32 + nt * 8 + 2 * tig]     = p0[nt];
                red[wm][wn * 32 + nt * 8 + 2 * tig + 1] = p1[nt];
            }
        }
        __syncthreads();
        if (tid < 64)
            xacc[tid] += red[0][tid] + red[1][tid] + red[2][tid] + red[3][tid];
        __syncthreads();
    }

    if (tid < 64) g_xconv[(size_t)bl * F_ + n0 + tid] = xacc[tid];
}

// ---------------------------------------------------------------------------
// Kernel 3: head MLP per (b,l): 384->128 gelu ->64 gelu ->1 ; pred * mask
// ---------------------------------------------------------------------------
__global__ void __launch_bounds__(128) head_kernel(
    const float* __restrict__ hw1, const float* __restrict__ hb1,
    const float* __restrict__ hw2, const float* __restrict__ hb2,
    const float* __restrict__ hw3, const float* __restrict__ hb3,
    const float* __restrict__ mask) {
    const int bl = blockIdx.x;
    const int tid = threadIdx.x;
    __shared__ float xs[F_];
    __shared__ float h1[H_];
    __shared__ float h2[H_ / 2];

    for (int i = tid; i < F_; i += 128) xs[i] = g_xconv[(size_t)bl * F_ + i];
    __syncthreads();

    float s = hb1[tid];
    for (int f = 0; f < F_; ++f) s += xs[f] * hw1[f * H_ + tid];
    h1[tid] = gelu_f(s);
    __syncthreads();

    if (tid < 64) {
        float s2 = hb2[tid];
#pragma unroll 4
        for (int h = 0; h < H_; ++h) s2 += h1[h] * hw2[h * 64 + tid];
        h2[tid] = gelu_f(s2);
    }
    __syncthreads();

    if (tid == 0) {
        float p = hb3[0];
        for (int j = 0; j < 64; ++j) p += h2[j] * hw3[j];
        g_predm[bl] = p * mask[bl];
    }
}

// ---------------------------------------------------------------------------
// Kernel 4: per-batch masked reduction
// ---------------------------------------------------------------------------
__global__ void __launch_bounds__(128) reduce_kernel(const float* __restrict__ mask,
                                                     float* __restrict__ out) {
    const int b = blockIdx.x;
    const int tid = threadIdx.x;
    __shared__ float sp[128];
    __shared__ float smk[128];

    float p = 0.f, mk = 0.f;
    for (int l = tid; l < L_; l += 128) {
        p += g_predm[b * L_ + l];
        mk += mask[b * L_ + l];
    }
    sp[tid] = p; smk[tid] = mk;
    __syncthreads();
    for (int s = 64; s > 0; s >>= 1) {
        if (tid < s) { sp[tid] += sp[tid + s]; smk[tid] += smk[tid + s]; }
        __syncthreads();
    }
    if (tid == 0) {
        float vl = smk[0] < 1.f ? 1.f : smk[0];
        out[b] = sp[0] / sqrtf(vl);
    }
}

// ---------------------------------------------------------------------------
// Launch
// ---------------------------------------------------------------------------
extern "C" void kernel_launch(void* const* d_in, const int* in_sizes, int n_in,
                              void* d_out, int out_size) {
    const float* h_V  = (const float*)d_in[0];
    const float* h_E  = (const float*)d_in[1];
    const float* mask = (const float*)d_in[2];
    const float* fw1  = (const float*)d_in[3];
    const float* fb1  = (const float*)d_in[4];
    const float* fw2  = (const float*)d_in[5];
    const float* fb2  = (const float*)d_in[6];
    const float* hw1  = (const float*)d_in[7];
    const float* hb1  = (const float*)d_in[8];
    const float* hw2  = (const float*)d_in[9];
    const float* hb2  = (const float*)d_in[10];
    const float* hw3  = (const float*)d_in[11];
    const float* hb3  = (const float*)d_in[12];
    float* out = (float*)d_out;

    conv_hE<<<((size_t)M1_ * H_) / (256 * 4), 256>>>(h_E);
    transpose_w<<<(F_ * H_ + F_ * F_ + 255) / 256, 256>>>(fw1, fw2);

    dim3 g1(F_ / 64, M1_ / 128);             // (6, 4608)
    gemm1_mma<<<g1, 256, SMEM1>>>(fb1);

    dim3 g2(F_ / 64, B_ * L_);               // (6, 1536)
    gemm2_mma<<<g2, 256, SMEM2>>>(h_V, fb2);

    head_kernel<<<B_ * L_, 128>>>(hw1, hb1, hw2, hb2, hw3, hb3, mask);
    reduce_kernel<<<B_, 128>>>(mask, out);
}

// round 12
// speedup vs baseline: 1.7149x; 1.7149x over previous
#include <cuda_runtime.h>
#include <cuda_fp16.h>
#include <math.h>
#include <stdint.h>

// ---------------------------------------------------------------------------
// Problem constants
// ---------------------------------------------------------------------------
#define B_  4
#define L_  384
#define H_  128
#define F_  384
#define M1_ (B_ * L_ * L_)      // 589824 edge rows

// ---------------------------------------------------------------------------
// Device scratch (allocation-free rule)
// ---------------------------------------------------------------------------
__device__ __half g_hEh[(size_t)M1_ * H_];      // fp16 copy of h_E
__device__ __half g_T1h[(size_t)M1_ * F_];      // fp16 gelu(h_E @ fw1 + fb1)
__device__ float  g_xconv[(size_t)B_ * L_ * F_];
__device__ float  g_predm[B_ * L_];
__device__ __half g_fw1T[F_ * H_];              // [n=384][k=128] fp16
__device__ __half g_fw2T[F_ * F_];              // [n=384][k=384] fp16

__device__ __forceinline__ float gelu_f(float x) {
    return 0.5f * x * (1.0f + erff(x * 0.70710678118654752440f));
}

__device__ __forceinline__ uint32_t smem_u32(const void* p) {
    uint32_t a;
    asm("{ .reg .u64 t; cvta.to.shared.u64 t, %1; cvt.u32.u64 %0, t; }" : "=r"(a) : "l"(p));
    return a;
}

// m16n8k16 fp16 MMA, fp32 accumulate.
__device__ __forceinline__ void mma16(float* c, const uint32_t* a, uint32_t b0, uint32_t b1) {
    asm volatile(
        "mma.sync.aligned.m16n8k16.row.col.f32.f16.f16.f32 "
        "{%0,%1,%2,%3}, {%4,%5,%6,%7}, {%8,%9}, {%0,%1,%2,%3};"
        : "+f"(c[0]), "+f"(c[1]), "+f"(c[2]), "+f"(c[3])
        : "r"(a[0]), "r"(a[1]), "r"(a[2]), "r"(a[3]), "r"(b0), "r"(b1));
}

__device__ __forceinline__ void ldsm4(uint32_t& r0, uint32_t& r1, uint32_t& r2,
                                      uint32_t& r3, uint32_t addr) {
    asm volatile("ldmatrix.sync.aligned.m8n8.x4.shared.b16 {%0,%1,%2,%3}, [%4];"
                 : "=r"(r0), "=r"(r1), "=r"(r2), "=r"(r3) : "r"(addr));
}

#define CP_COMMIT() asm volatile("cp.async.commit_group;" ::: "memory")
#define CP_WAIT1()  asm volatile("cp.async.wait_group 1;" ::: "memory")
#define CP_WAIT0()  asm volatile("cp.async.wait_group 0;" ::: "memory")

// Stage [128 rows x 32 half] (gmem row stride ldg halves), smem row pitch 80 B.
__device__ __forceinline__ void stage128(const __half* __restrict__ g, int ldg,
                                         uint32_t s_addr, int tid) {
#pragma unroll
    for (int i = 0; i < 2; ++i) {
        int idx = tid + i * 256;
        int row = idx >> 2, q = idx & 3;
        uint32_t dst = s_addr + (uint32_t)(row * 80 + q * 16);
        const __half* src = g + (size_t)row * ldg + q * 8;
        asm volatile("cp.async.cg.shared.global [%0], [%1], 16;" :: "r"(dst), "l"(src));
    }
}

// ---------------------------------------------------------------------------
// Dynamic smem layout (bytes): 4-stage ring for A and B (each 128x40 half)
// ---------------------------------------------------------------------------
#define SA_   10240
#define O_A   0                      // 4 x SA_
#define O_B   (4 * SA_)              // 4 x SA_
#define O_BIAS (8 * SA_)             // 128 floats
#define O_RED  (O_BIAS + 512)        // 4 x 128 floats (gemm2)
#define O_XACC (O_RED + 2048)        // 128 floats (gemm2)
#define SMEM1  (O_BIAS + 512)
#define SMEM2  (O_XACC + 512)

// ---------------------------------------------------------------------------
// Kernel 0a: convert h_E (fp32) -> fp16
// ---------------------------------------------------------------------------
__global__ void __launch_bounds__(256) conv_hE(const float* __restrict__ hE) {
    size_t i = ((size_t)blockIdx.x * 256 + threadIdx.x) * 4;
    float4 v = *reinterpret_cast<const float4*>(hE + i);
    *reinterpret_cast<__half2*>(g_hEh + i)     = __floats2half2_rn(v.x, v.y);
    *reinterpret_cast<__half2*>(g_hEh + i + 2) = __floats2half2_rn(v.z, v.w);
}

// ---------------------------------------------------------------------------
// Kernel 0b: transpose weights to [n][k] fp16
// ---------------------------------------------------------------------------
__global__ void __launch_bounds__(256) transpose_w(const float* __restrict__ fw1,
                                                   const float* __restrict__ fw2) {
    int idx = blockIdx.x * 256 + threadIdx.x;
    if (idx < F_ * H_) {
        int n = idx / H_, k = idx % H_;
        g_fw1T[idx] = __float2half_rn(fw1[k * F_ + n]);
    }
    int i2 = idx - F_ * H_;
    if (i2 >= 0 && i2 < F_ * F_) {
        int n = i2 / F_, k = i2 % F_;
        g_fw2T[i2] = __float2half_rn(fw2[k * F_ + n]);
    }
}

// ---------------------------------------------------------------------------
// Fragment set for one K=16 step of the 32x64 warp tile.
//   a[mt][4]  : two 16x16 A tiles (ldsm4 each)
//   b[ntp][4] : four ldsm4, each = 2 n-tiles (8 rows) x 2 k-halves:
//               r0=(n_lo,k_lo) r1=(n_lo,k_hi) r2=(n_hi,k_lo) r3=(n_hi,k_hi)
// ---------------------------------------------------------------------------
struct FragSet { uint32_t a[2][4]; uint32_t b[4][4]; };

__device__ __forceinline__ void load_frags(FragSet& f, uint32_t aA, uint32_t aB,
                                           uint32_t aoffA, uint32_t aoffB, int ks) {
#pragma unroll
    for (int mt = 0; mt < 2; ++mt)
        ldsm4(f.a[mt][0], f.a[mt][1], f.a[mt][2], f.a[mt][3],
              aA + aoffA + mt * 1280 + ks * 32);
#pragma unroll
    for (int ntp = 0; ntp < 4; ++ntp)
        ldsm4(f.b[ntp][0], f.b[ntp][1], f.b[ntp][2], f.b[ntp][3],
              aB + aoffB + ntp * 1280 + ks * 32);
}

__device__ __forceinline__ void mma_step(FragSet& f, float acc[2][8][4]) {
#pragma unroll
    for (int mt = 0; mt < 2; ++mt)
#pragma unroll
        for (int nt = 0; nt < 8; ++nt) {
            const int ntp = nt >> 1;
            if (nt & 1) mma16(acc[mt][nt], f.a[mt], f.b[ntp][2], f.b[ntp][3]);
            else        mma16(acc[mt][nt], f.a[mt], f.b[ntp][0], f.b[ntp][1]);
        }
}

// ---------------------------------------------------------------------------
// Software-pipelined mainloop: 4-stage cp.async ring, chunks kc & kc+1 always
// resident, register frag double-buffer, ONE barrier per chunk.
// ---------------------------------------------------------------------------
template <int NC>
__device__ __forceinline__ void mainloop(const __half* __restrict__ Ab, int ldgA,
                                         const __half* __restrict__ Bb, int ldgB,
                                         uint32_t sb, int tid,
                                         uint32_t aoffA, uint32_t aoffB,
                                         float acc[2][8][4]) {
    stage128(Ab, ldgA, sb + O_A, tid);
    stage128(Bb, ldgB, sb + O_B, tid);
    CP_COMMIT();
    stage128(Ab + 32, ldgA, sb + O_A + SA_, tid);
    stage128(Bb + 32, ldgB, sb + O_B + SA_, tid);
    CP_COMMIT();
    stage128(Ab + 64, ldgA, sb + O_A + 2 * SA_, tid);
    stage128(Bb + 64, ldgB, sb + O_B + 2 * SA_, tid);
    CP_COMMIT();
    CP_WAIT1();                      // chunks 0,1 resident; 2 in flight
    __syncthreads();

    FragSet f0, f1;
    load_frags(f0, sb + O_A, sb + O_B, aoffA, aoffB, 0);

#pragma unroll
    for (int kc = 0; kc < NC; ++kc) {
        const uint32_t aA = sb + O_A + (kc & 3) * SA_;
        const uint32_t aB = sb + O_B + (kc & 3) * SA_;
        load_frags(f1, aA, aB, aoffA, aoffB, 1);       // ks1 of chunk kc
        mma_step(f0, acc);
        if (kc + 1 < NC) {                              // ks0 of chunk kc+1 (resident)
            load_frags(f0, sb + O_A + ((kc + 1) & 3) * SA_,
                           sb + O_B + ((kc + 1) & 3) * SA_, aoffA, aoffB, 0);
        }
        mma_step(f1, acc);
        if (kc + 3 < NC) {                              // refill ring (stage of chunk kc-1)
            stage128(Ab + (kc + 3) * 32, ldgA, sb + O_A + ((kc + 3) & 3) * SA_, tid);
            stage128(Bb + (kc + 3) * 32, ldgB, sb + O_B + ((kc + 3) & 3) * SA_, tid);
            CP_COMMIT();
            CP_WAIT1();                                 // chunk kc+2 resident
        } else if (kc + 2 < NC) {
            CP_WAIT0();                                 // drain tail
        }
        __syncthreads();
    }
}

// ---------------------------------------------------------------------------
// Kernel 1: T1 = fp16(gelu(h_E @ fw1 + fb1))
//   grid (3, 4608). CTA 128x128, 8 warps (wm4 x wn2), warp tile 32x64.
// ---------------------------------------------------------------------------
__global__ void __launch_bounds__(256, 2) gemm1_mma(const float* __restrict__ fb1) {
    extern __shared__ char smc[];
    const uint32_t sb = smem_u32(smc);
    float* biasS = reinterpret_cast<float*>(smc + O_BIAS);

    const int tid = threadIdx.x;
    const int wid = tid >> 5, lane = tid & 31;
    const int gid = lane >> 2, tig = lane & 3;
    const int g8 = lane >> 3, lr = lane & 7;
    const int wm = wid & 3, wn = wid >> 2;
    const int m0 = blockIdx.y * 128, n0 = blockIdx.x * 128;

    const uint32_t aoffA = (uint32_t)((wm * 32 + (g8 & 1) * 8 + lr) * 80 + (g8 >> 1) * 16);
    const uint32_t aoffB = (uint32_t)((wn * 64 + (g8 >> 1) * 8 + lr) * 80 + (g8 & 1) * 16);

    if (tid < 128) biasS[tid] = fb1[n0 + tid];

    float acc[2][8][4];
#pragma unroll
    for (int mt = 0; mt < 2; ++mt)
#pragma unroll
        for (int nt = 0; nt < 8; ++nt)
#pragma unroll
            for (int j = 0; j < 4; ++j) acc[mt][nt][j] = 0.f;

    mainloop<4>(g_hEh + (size_t)m0 * H_, H_, g_fw1T + (size_t)n0 * H_, H_,
                sb, tid, aoffA, aoffB, acc);

    // Epilogue: bias + exact-erf gelu, fp16 half2 stores
#pragma unroll
    for (int mt = 0; mt < 2; ++mt)
#pragma unroll
        for (int nt = 0; nt < 8; ++nt) {
            float* c = acc[mt][nt];
            int lrr = wm * 32 + mt * 16 + gid;
            int lc = wn * 64 + nt * 8 + 2 * tig;
            float b0v = biasS[lc], b1v = biasS[lc + 1];
            size_t base = (size_t)(m0 + lrr) * F_ + n0 + lc;
            *reinterpret_cast<__half2*>(g_T1h + base) =
                __floats2half2_rn(gelu_f(c[0] + b0v), gelu_f(c[1] + b1v));
            *reinterpret_cast<__half2*>(g_T1h + base + (size_t)8 * F_) =
                __floats2half2_rn(gelu_f(c[2] + b0v), gelu_f(c[3] + b1v));
        }
}

// ---------------------------------------------------------------------------
// Kernel 2: per (bl, n-tile): T2 = gelu(T1_bl @ fw2 + fb2);
//           xconv[bl, n] = sum_k hV[b,k,n] * T2[k,n]
//   grid (3, 1536). 3 m-tiles of 128 k-edges, K=384 in 12 chunks.
// ---------------------------------------------------------------------------
__global__ void __launch_bounds__(256, 2) gemm2_mma(const float* __restrict__ hV,
                                                    const float* __restrict__ fb2) {
    extern __shared__ char smc[];
    const uint32_t sb = smem_u32(smc);
    float* biasS = reinterpret_cast<float*>(smc + O_BIAS);
    float (*red)[128] = reinterpret_cast<float (*)[128]>(smc + O_RED);
    float* xacc = reinterpret_cast<float*>(smc + O_XACC);

    const int tid = threadIdx.x;
    const int wid = tid >> 5, lane = tid & 31;
    const int gid = lane >> 2, tig = lane & 3;
    const int g8 = lane >> 3, lr = lane & 7;
    const int wm = wid & 3, wn = wid >> 2;
    const int bl = blockIdx.y, b = bl / L_;
    const int n0 = blockIdx.x * 128;

    const uint32_t aoffA = (uint32_t)((wm * 32 + (g8 & 1) * 8 + lr) * 80 + (g8 >> 1) * 16);
    const uint32_t aoffB = (uint32_t)((wn * 64 + (g8 >> 1) * 8 + lr) * 80 + (g8 & 1) * 16);

    if (tid < 128) { biasS[tid] = fb2[n0 + tid]; xacc[tid] = 0.f; }
    __syncthreads();

    const __half* Bbase = g_fw2T + (size_t)n0 * F_;

    for (int mt = 0; mt < 3; ++mt) {
        float acc[2][8][4];
#pragma unroll
        for (int m2 = 0; m2 < 2; ++m2)
#pragma unroll
            for (int nt = 0; nt < 8; ++nt)
#pragma unroll
                for (int j = 0; j < 4; ++j) acc[m2][nt][j] = 0.f;

        mainloop<12>(g_T1h + (size_t)(bl * L_ + mt * 128) * F_, F_, Bbase, F_,
                     sb, tid, aoffA, aoffB, acc);

        // Fused epilogue: gelu + bias, * hV, reduce over the 128 k-edge rows
        float p0[8], p1[8];
#pragma unroll
        for (int nt = 0; nt < 8; ++nt) { p0[nt] = 0.f; p1[nt] = 0.f; }

#pragma unroll
        for (int m2 = 0; m2 < 2; ++m2)
#pragma unroll
            for (int nt = 0; nt < 8; ++nt) {
                float* c = acc[m2][nt];
                int r0 = wm * 32 + m2 * 16 + gid;
                int lc = wn * 64 + nt * 8 + 2 * tig;
                float b0v = biasS[lc], b1v = biasS[lc + 1];
                const float* hv0 = hV + ((size_t)b * L_ + mt * 128 + r0) * F_ + n0 + lc;
                float2 h0 = *reinterpret_cast<const float2*>(hv0);
                float2 h1 = *reinterpret_cast<const float2*>(hv0 + (size_t)8 * F_);
                p0[nt] += gelu_f(c[0] + b0v) * h0.x + gelu_f(c[2] + b0v) * h1.x;
                p1[nt] += gelu_f(c[1] + b1v) * h0.y + gelu_f(c[3] + b1v) * h1.y;
            }

        // butterfly over gid (lane bits 2..4)
#pragma unroll
        for (int nt = 0; nt < 8; ++nt) {
#pragma unroll
            for (int off = 16; off >= 4; off >>= 1) {
                p0[nt] += __shfl_xor_sync(0xFFFFFFFFu, p0[nt], off);
                p1[nt] += __shfl_xor_sync(0xFFFFFFFFu, p1[nt], off);
            }
        }
        if (gid == 0) {
#pragma unroll
            for (int nt = 0; nt < 8; ++nt) {
                red[wm][wn * 64 + nt * 8 + 2 * tig]     = p0[nt];
                red[wm][wn * 64 + nt * 8 + 2 * tig + 1] = p1[nt];
            }
        }
        __syncthreads();
        if (tid < 128)
            xacc[tid] += red[0][tid] + red[1][tid] + red[2][tid] + red[3][tid];
        __syncthreads();
    }

    if (tid < 128) g_xconv[(size_t)bl * F_ + n0 + tid] = xacc[tid];
}

// ---------------------------------------------------------------------------
// Kernel 3: head MLP per (b,l): 384->128 gelu ->64 gelu ->1 ; pred * mask
// ---------------------------------------------------------------------------
__global__ void __launch_bounds__(128) head_kernel(
    const float* __restrict__ hw1, const float* __restrict__ hb1,
    const float* __restrict__ hw2, const float* __restrict__ hb2,
    const float* __restrict__ hw3, const float* __restrict__ hb3,
    const float* __restrict__ mask) {
    const int bl = blockIdx.x;
    const int tid = threadIdx.x;
    __shared__ float xs[F_];
    __shared__ float h1[H_];
    __shared__ float h2[H_ / 2];

    for (int i = tid; i < F_; i += 128) xs[i] = g_xconv[(size_t)bl * F_ + i];
    __syncthreads();

    float s = hb1[tid];
    for (int f = 0; f < F_; ++f) s += xs[f] * hw1[f * H_ + tid];
    h1[tid] = gelu_f(s);
    __syncthreads();

    if (tid < 64) {
        float s2 = hb2[tid];
#pragma unroll 4
        for (int h = 0; h < H_; ++h) s2 += h1[h] * hw2[h * 64 + tid];
        h2[tid] = gelu_f(s2);
    }
    __syncthreads();

    if (tid == 0) {
        float p = hb3[0];
        for (int j = 0; j < 64; ++j) p += h2[j] * hw3[j];
        g_predm[bl] = p * mask[bl];
    }
}

// ---------------------------------------------------------------------------
// Kernel 4: per-batch masked reduction
// ---------------------------------------------------------------------------
__global__ void __launch_bounds__(128) reduce_kernel(const float* __restrict__ mask,
                                                     float* __restrict__ out) {
    const int b = blockIdx.x;
    const int tid = threadIdx.x;
    __shared__ float sp[128];
    __shared__ float smk[128];

    float p = 0.f, mk = 0.f;
    for (int l = tid; l < L_; l += 128) {
        p += g_predm[b * L_ + l];
        mk += mask[b * L_ + l];
    }
    sp[tid] = p; smk[tid] = mk;
    __syncthreads();
    for (int s = 64; s > 0; s >>= 1) {
        if (tid < s) { sp[tid] += sp[tid + s]; smk[tid] += smk[tid + s]; }
        __syncthreads();
    }
    if (tid == 0) {
        float vl = smk[0] < 1.f ? 1.f : smk[0];
        out[b] = sp[0] / sqrtf(vl);
    }
}

// ---------------------------------------------------------------------------
// Launch
// ---------------------------------------------------------------------------
extern "C" void kernel_launch(void* const* d_in, const int* in_sizes, int n_in,
                              void* d_out, int out_size) {
    const float* h_V  = (const float*)d_in[0];
    const float* h_E  = (const float*)d_in[1];
    const float* mask = (const float*)d_in[2];
    const float* fw1  = (const float*)d_in[3];
    const float* fb1  = (const float*)d_in[4];
    const float* fw2  = (const float*)d_in[5];
    const float* fb2  = (const float*)d_in[6];
    const float* hw1  = (const float*)d_in[7];
    const float* hb1  = (const float*)d_in[8];
    const float* hw2  = (const float*)d_in[9];
    const float* hb2  = (const float*)d_in[10];
    const float* hw3  = (const float*)d_in[11];
    const float* hb3  = (const float*)d_in[12];
    float* out = (float*)d_out;

    static int configured = 0;
    if (!configured) {
        cudaFuncSetAttribute(gemm1_mma, cudaFuncAttributeMaxDynamicSharedMemorySize, SMEM1);
        cudaFuncSetAttribute(gemm2_mma, cudaFuncAttributeMaxDynamicSharedMemorySize, SMEM2);
        configured = 1;
    }

    conv_hE<<<((size_t)M1_ * H_) / (256 * 4), 256>>>(h_E);
    transpose_w<<<(F_ * H_ + F_ * F_ + 255) / 256, 256>>>(fw1, fw2);

    dim3 g1(F_ / 128, M1_ / 128);            // (3, 4608)
    gemm1_mma<<<g1, 256, SMEM1>>>(fb1);

    dim3 g2(F_ / 128, B_ * L_);              // (3, 1536)
    gemm2_mma<<<g2, 256, SMEM2>>>(h_V, fb2);

    head_kernel<<<B_ * L_, 128>>>(hw1, hb1, hw2, hb2, hw3, hb3, mask);
    reduce_kernel<<<B_, 128>>>(mask, out);
}

// round 13
// speedup vs baseline: 1.8846x; 1.0990x over previous
#include <cuda_runtime.h>
#include <cuda_fp16.h>
#include <math.h>
#include <stdint.h>

// ---------------------------------------------------------------------------
// Problem constants
// ---------------------------------------------------------------------------
#define B_  4
#define L_  384
#define H_  128
#define F_  384
#define M1_ (B_ * L_ * L_)      // 589824 edge rows

// ---------------------------------------------------------------------------
// Device scratch (allocation-free rule)
// ---------------------------------------------------------------------------
__device__ __half g_hEh[(size_t)M1_ * H_];      // fp16 copy of h_E
__device__ __half g_T1h[(size_t)M1_ * F_];      // fp16 gelu(h_E @ fw1 + fb1)
__device__ float  g_xconv[(size_t)B_ * L_ * F_];
__device__ float  g_predm[B_ * L_];
__device__ __half g_fw1T[F_ * H_];              // [n=384][k=128] fp16
__device__ __half g_fw2T[F_ * F_];              // [n=384][k=384] fp16

__device__ __forceinline__ float gelu_f(float x) {
    return 0.5f * x * (1.0f + erff(x * 0.70710678118654752440f));
}

__device__ __forceinline__ uint32_t smem_u32(const void* p) {
    uint32_t a;
    asm("{ .reg .u64 t; cvta.to.shared.u64 t, %1; cvt.u32.u64 %0, t; }" : "=r"(a) : "l"(p));
    return a;
}

// m16n8k16 fp16 MMA, fp32 accumulate.
__device__ __forceinline__ void mma16(float* c, const uint32_t* a, uint32_t b0, uint32_t b1) {
    asm volatile(
        "mma.sync.aligned.m16n8k16.row.col.f32.f16.f16.f32 "
        "{%0,%1,%2,%3}, {%4,%5,%6,%7}, {%8,%9}, {%0,%1,%2,%3};"
        : "+f"(c[0]), "+f"(c[1]), "+f"(c[2]), "+f"(c[3])
        : "r"(a[0]), "r"(a[1]), "r"(a[2]), "r"(a[3]), "r"(b0), "r"(b1));
}

__device__ __forceinline__ void ldsm4(uint32_t& r0, uint32_t& r1, uint32_t& r2,
                                      uint32_t& r3, uint32_t addr) {
    asm volatile("ldmatrix.sync.aligned.m8n8.x4.shared.b16 {%0,%1,%2,%3}, [%4];"
                 : "=r"(r0), "=r"(r1), "=r"(r2), "=r"(r3) : "r"(addr));
}

#define CP_COMMIT() asm volatile("cp.async.commit_group;" ::: "memory")
#define CP_WAIT1()  asm volatile("cp.async.wait_group 1;" ::: "memory")
#define CP_WAIT0()  asm volatile("cp.async.wait_group 0;" ::: "memory")

// ---------------------------------------------------------------------------
// Swizzled chunk buffer: 128 rows x 32 halves, 64B pitch, 8KB.
//   phys 16B-col = q ^ ((row>>1)&3)  -> ldmatrix 8-row reads are conflict-free
// ---------------------------------------------------------------------------
#define CH_   8192
#define O_A   0                       // 6 chunk slots
#define O_B   (6 * CH_)               // 6 chunk slots
#define O_BIAS (12 * CH_)             // 128 floats
#define O_RED  (O_BIAS + 512)         // 4 x 128 floats (gemm2)
#define O_XACC (O_RED + 2048)         // 128 floats (gemm2)
#define SMEM1  (O_BIAS + 512)
#define SMEM2  (O_XACC + 512)

__device__ __forceinline__ uint32_t swa(uint32_t chunkbase, int R, int qlog) {
    return chunkbase + (uint32_t)(R * 64) + (uint32_t)((qlog ^ ((R >> 1) & 3)) << 4);
}

// Stage one chunk: [128 rows x 32 half], gmem row stride ldg halves.
__device__ __forceinline__ void stage_sw(const __half* __restrict__ g, int ldg,
                                         uint32_t s_addr, int tid) {
#pragma unroll
    for (int i = 0; i < 2; ++i) {
        int idx = tid + i * 256;
        int row = idx >> 2, q = idx & 3;
        uint32_t dst = s_addr + (uint32_t)(row * 64) + (uint32_t)((q ^ ((row >> 1) & 3)) << 4);
        const __half* src = g + (size_t)row * ldg + q * 8;
        asm volatile("cp.async.cg.shared.global [%0], [%1], 16;" :: "r"(dst), "l"(src));
    }
}

// ---------------------------------------------------------------------------
// Kernel 0a: convert h_E (fp32) -> fp16
// ---------------------------------------------------------------------------
__global__ void __launch_bounds__(256) conv_hE(const float* __restrict__ hE) {
    size_t i = ((size_t)blockIdx.x * 256 + threadIdx.x) * 4;
    float4 v = *reinterpret_cast<const float4*>(hE + i);
    *reinterpret_cast<__half2*>(g_hEh + i)     = __floats2half2_rn(v.x, v.y);
    *reinterpret_cast<__half2*>(g_hEh + i + 2) = __floats2half2_rn(v.z, v.w);
}

// ---------------------------------------------------------------------------
// Kernel 0b: transpose weights to [n][k] fp16
// ---------------------------------------------------------------------------
__global__ void __launch_bounds__(256) transpose_w(const float* __restrict__ fw1,
                                                   const float* __restrict__ fw2) {
    int idx = blockIdx.x * 256 + threadIdx.x;
    if (idx < F_ * H_) {
        int n = idx / H_, k = idx % H_;
        g_fw1T[idx] = __float2half_rn(fw1[k * F_ + n]);
    }
    int i2 = idx - F_ * H_;
    if (i2 >= 0 && i2 < F_ * F_) {
        int n = i2 / F_, k = i2 % F_;
        g_fw2T[i2] = __float2half_rn(fw2[k * F_ + n]);
    }
}

// ---------------------------------------------------------------------------
// Fragment set for one K=16 step of the 32x64 warp tile.
// ---------------------------------------------------------------------------
struct FragSet { uint32_t a[2][4]; uint32_t b[4][4]; };

__device__ __forceinline__ void load_frags(FragSet& f, uint32_t aA, uint32_t aB,
                                           int rowA, int qhA, int rowB, int qhB,
                                           int ks) {
#pragma unroll
    for (int mt = 0; mt < 2; ++mt)
        ldsm4(f.a[mt][0], f.a[mt][1], f.a[mt][2], f.a[mt][3],
              swa(aA, rowA + mt * 16, qhA + 2 * ks));
#pragma unroll
    for (int ntp = 0; ntp < 4; ++ntp)
        ldsm4(f.b[ntp][0], f.b[ntp][1], f.b[ntp][2], f.b[ntp][3],
              swa(aB, rowB + ntp * 16, qhB + 2 * ks));
}

__device__ __forceinline__ void mma_step(FragSet& f, float acc[2][8][4]) {
#pragma unroll
    for (int mt = 0; mt < 2; ++mt)
#pragma unroll
        for (int nt = 0; nt < 8; ++nt) {
            const int ntp = nt >> 1;
            if (nt & 1) mma16(acc[mt][nt], f.a[mt], f.b[ntp][2], f.b[ntp][3]);
            else        mma16(acc[mt][nt], f.a[mt], f.b[ntp][0], f.b[ntp][1]);
        }
}

// ---------------------------------------------------------------------------
// Pair-pipelined mainloop: K processed in NP pairs of 32-chunks (K=64/pair),
// 6-slot smem ring per operand, ONE barrier per pair, 64-MMA bursts.
// Invariants: entering pair p, pairs p (and p+1 after first wait) are
// resident+published; staging pair p+2 overwrites pair p-1's slots (safe:
// all warps passed the end-of-(p-1) barrier).
// ---------------------------------------------------------------------------
#define CHA(c) (sb + O_A + ((c) % 6) * CH_)
#define CHB(c) (sb + O_B + ((c) % 6) * CH_)

template <int NP>
__device__ __forceinline__ void mainloop(const __half* __restrict__ Ab, int ldgA,
                                         const __half* __restrict__ Bb, int ldgB,
                                         uint32_t sb, int tid,
                                         int rowA, int qhA, int rowB, int qhB,
                                         float acc[2][8][4]) {
    stage_sw(Ab,      ldgA, CHA(0), tid);
    stage_sw(Ab + 32, ldgA, CHA(1), tid);
    stage_sw(Bb,      ldgB, CHB(0), tid);
    stage_sw(Bb + 32, ldgB, CHB(1), tid);
    CP_COMMIT();
    if (NP > 1) {
        stage_sw(Ab + 64, ldgA, CHA(2), tid);
        stage_sw(Ab + 96, ldgA, CHA(3), tid);
        stage_sw(Bb + 64, ldgB, CHB(2), tid);
        stage_sw(Bb + 96, ldgB, CHB(3), tid);
        CP_COMMIT();
        CP_WAIT1();
    } else {
        CP_WAIT0();
    }
    __syncthreads();

    FragSet f0, f1;
    load_frags(f0, CHA(0), CHB(0), rowA, qhA, rowB, qhB, 0);

#pragma unroll
    for (int p = 0; p < NP; ++p) {
        const int c0 = 2 * p, c1 = 2 * p + 1;
        load_frags(f1, CHA(c0), CHB(c0), rowA, qhA, rowB, qhB, 1);
        mma_step(f0, acc);
        load_frags(f0, CHA(c1), CHB(c1), rowA, qhA, rowB, qhB, 0);
        mma_step(f1, acc);
        load_frags(f1, CHA(c1), CHB(c1), rowA, qhA, rowB, qhB, 1);
        mma_step(f0, acc);
        mma_step(f1, acc);

        if (p + 2 < NP) {
            stage_sw(Ab + (2 * p + 4) * 32, ldgA, CHA(2 * p + 4), tid);
            stage_sw(Ab + (2 * p + 5) * 32, ldgA, CHA(2 * p + 5), tid);
            stage_sw(Bb + (2 * p + 4) * 32, ldgB, CHB(2 * p + 4), tid);
            stage_sw(Bb + (2 * p + 5) * 32, ldgB, CHB(2 * p + 5), tid);
            CP_COMMIT();
            CP_WAIT1();
        } else if (p + 1 < NP) {
            CP_WAIT0();
        }
        if (p + 1 < NP) {
            __syncthreads();
            load_frags(f0, CHA(2 * p + 2), CHB(2 * p + 2), rowA, qhA, rowB, qhB, 0);
        }
    }
}

// ---------------------------------------------------------------------------
// Kernel 1: T1 = fp16(gelu(h_E @ fw1 + fb1))
//   grid (3, 4608). CTA 128x128, 8 warps (wm4 x wn2), warp tile 32x64.
//   K=128 = 2 pairs -> 2 barriers total.
// ---------------------------------------------------------------------------
__global__ void __launch_bounds__(256, 2) gemm1_mma(const float* __restrict__ fb1) {
    extern __shared__ char smc[];
    const uint32_t sb = smem_u32(smc);
    float* biasS = reinterpret_cast<float*>(smc + O_BIAS);

    const int tid = threadIdx.x;
    const int wid = tid >> 5, lane = tid & 31;
    const int gid = lane >> 2, tig = lane & 3;
    const int g8 = lane >> 3, lr = lane & 7;
    const int wm = wid & 3, wn = wid >> 2;
    const int m0 = blockIdx.y * 128, n0 = blockIdx.x * 128;

    const int rowA = wm * 32 + (g8 & 1) * 8 + lr, qhA = g8 >> 1;
    const int rowB = wn * 64 + (g8 >> 1) * 8 + lr, qhB = g8 & 1;

    if (tid < 128) biasS[tid] = fb1[n0 + tid];

    float acc[2][8][4];
#pragma unroll
    for (int mt = 0; mt < 2; ++mt)
#pragma unroll
        for (int nt = 0; nt < 8; ++nt)
#pragma unroll
            for (int j = 0; j < 4; ++j) acc[mt][nt][j] = 0.f;

    mainloop<2>(g_hEh + (size_t)m0 * H_, H_, g_fw1T + (size_t)n0 * H_, H_,
                sb, tid, rowA, qhA, rowB, qhB, acc);

    // Epilogue: bias + exact-erf gelu, fp16 half2 stores
#pragma unroll
    for (int mt = 0; mt < 2; ++mt)
#pragma unroll
        for (int nt = 0; nt < 8; ++nt) {
            float* c = acc[mt][nt];
            int lrr = wm * 32 + mt * 16 + gid;
            int lc = wn * 64 + nt * 8 + 2 * tig;
            float b0v = biasS[lc], b1v = biasS[lc + 1];
            size_t base = (size_t)(m0 + lrr) * F_ + n0 + lc;
            *reinterpret_cast<__half2*>(g_T1h + base) =
                __floats2half2_rn(gelu_f(c[0] + b0v), gelu_f(c[1] + b1v));
            *reinterpret_cast<__half2*>(g_T1h + base + (size_t)8 * F_) =
                __floats2half2_rn(gelu_f(c[2] + b0v), gelu_f(c[3] + b1v));
        }
}

// ---------------------------------------------------------------------------
// Kernel 2: per (bl, n-tile): T2 = gelu(T1_bl @ fw2 + fb2);
//           xconv[bl, n] = sum_k hV[b,k,n] * T2[k,n]
//   grid (3, 1536). 3 m-tiles of 128 k-edges, K=384 = 6 pairs -> 7 barriers.
// ---------------------------------------------------------------------------
__global__ void __launch_bounds__(256, 2) gemm2_mma(const float* __restrict__ hV,
                                                    const float* __restrict__ fb2) {
    extern __shared__ char smc[];
    const uint32_t sb = smem_u32(smc);
    float* biasS = reinterpret_cast<float*>(smc + O_BIAS);
    float (*red)[128] = reinterpret_cast<float (*)[128]>(smc + O_RED);
    float* xacc = reinterpret_cast<float*>(smc + O_XACC);

    const int tid = threadIdx.x;
    const int wid = tid >> 5, lane = tid & 31;
    const int gid = lane >> 2, tig = lane & 3;
    const int g8 = lane >> 3, lr = lane & 7;
    const int wm = wid & 3, wn = wid >> 2;
    const int bl = blockIdx.y, b = bl / L_;
    const int n0 = blockIdx.x * 128;

    const int rowA = wm * 32 + (g8 & 1) * 8 + lr, qhA = g8 >> 1;
    const int rowB = wn * 64 + (g8 >> 1) * 8 + lr, qhB = g8 & 1;

    if (tid < 128) { biasS[tid] = fb2[n0 + tid]; xacc[tid] = 0.f; }
    __syncthreads();

    const __half* Bbase = g_fw2T + (size_t)n0 * F_;

    for (int mt = 0; mt < 3; ++mt) {
        float acc[2][8][4];
#pragma unroll
        for (int m2 = 0; m2 < 2; ++m2)
#pragma unroll
            for (int nt = 0; nt < 8; ++nt)
#pragma unroll
                for (int j = 0; j < 4; ++j) acc[m2][nt][j] = 0.f;

        mainloop<6>(g_T1h + (size_t)(bl * L_ + mt * 128) * F_, F_, Bbase, F_,
                    sb, tid, rowA, qhA, rowB, qhB, acc);

        // Fused epilogue: gelu + bias, * hV, reduce over the 128 k-edge rows
        float p0[8], p1[8];
#pragma unroll
        for (int nt = 0; nt < 8; ++nt) { p0[nt] = 0.f; p1[nt] = 0.f; }

#pragma unroll
        for (int m2 = 0; m2 < 2; ++m2)
#pragma unroll
            for (int nt = 0; nt < 8; ++nt) {
                float* c = acc[m2][nt];
                int r0 = wm * 32 + m2 * 16 + gid;
                int lc = wn * 64 + nt * 8 + 2 * tig;
                float b0v = biasS[lc], b1v = biasS[lc + 1];
                const float* hv0 = hV + ((size_t)b * L_ + mt * 128 + r0) * F_ + n0 + lc;
                float2 h0 = *reinterpret_cast<const float2*>(hv0);
                float2 h1 = *reinterpret_cast<const float2*>(hv0 + (size_t)8 * F_);
                p0[nt] += gelu_f(c[0] + b0v) * h0.x + gelu_f(c[2] + b0v) * h1.x;
                p1[nt] += gelu_f(c[1] + b1v) * h0.y + gelu_f(c[3] + b1v) * h1.y;
            }

        // butterfly over gid (lane bits 2..4)
#pragma unroll
        for (int nt = 0; nt < 8; ++nt) {
#pragma unroll
            for (int off = 16; off >= 4; off >>= 1) {
                p0[nt] += __shfl_xor_sync(0xFFFFFFFFu, p0[nt], off);
                p1[nt] += __shfl_xor_sync(0xFFFFFFFFu, p1[nt], off);
            }
        }
        if (gid == 0) {
#pragma unroll
            for (int nt = 0; nt < 8; ++nt) {
                red[wm][wn * 64 + nt * 8 + 2 * tig]     = p0[nt];
                red[wm][wn * 64 + nt * 8 + 2 * tig + 1] = p1[nt];
            }
        }
        __syncthreads();
        if (tid < 128)
            xacc[tid] += red[0][tid] + red[1][tid] + red[2][tid] + red[3][tid];
        __syncthreads();
    }

    if (tid < 128) g_xconv[(size_t)bl * F_ + n0 + tid] = xacc[tid];
}

// ---------------------------------------------------------------------------
// Kernel 3: head MLP per (b,l): 384->128 gelu ->64 gelu ->1 ; pred * mask
// ---------------------------------------------------------------------------
__global__ void __launch_bounds__(128) head_kernel(
    const float* __restrict__ hw1, const float* __restrict__ hb1,
    const float* __restrict__ hw2, const float* __restrict__ hb2,
    const float* __restrict__ hw3, const float* __restrict__ hb3,
    const float* __restrict__ mask) {
    const int bl = blockIdx.x;
    const int tid = threadIdx.x;
    __shared__ float xs[F_];
    __shared__ float h1[H_];
    __shared__ float h2[H_ / 2];

    for (int i = tid; i < F_; i += 128) xs[i] = g_xconv[(size_t)bl * F_ + i];
    __syncthreads();

    float s = hb1[tid];
    for (int f = 0; f < F_; ++f) s += xs[f] * hw1[f * H_ + tid];
    h1[tid] = gelu_f(s);
    __syncthreads();

    if (tid < 64) {
        float s2 = hb2[tid];
#pragma unroll 4
        for (int h = 0; h < H_; ++h) s2 += h1[h] * hw2[h * 64 + tid];
        h2[tid] = gelu_f(s2);
    }
    __syncthreads();

    if (tid == 0) {
        float p = hb3[0];
        for (int j = 0; j < 64; ++j) p += h2[j] * hw3[j];
        g_predm[bl] = p * mask[bl];
    }
}

// ---------------------------------------------------------------------------
// Kernel 4: per-batch masked reduction
// ---------------------------------------------------------------------------
__global__ void __launch_bounds__(128) reduce_kernel(const float* __restrict__ mask,
                                                     float* __restrict__ out) {
    const int b = blockIdx.x;
    const int tid = threadIdx.x;
    __shared__ float sp[128];
    __shared__ float smk[128];

    float p = 0.f, mk = 0.f;
    for (int l = tid; l < L_; l += 128) {
        p += g_predm[b * L_ + l];
        mk += mask[b * L_ + l];
    }
    sp[tid] = p; smk[tid] = mk;
    __syncthreads();
    for (int s = 64; s > 0; s >>= 1) {
        if (tid < s) { sp[tid] += sp[tid + s]; smk[tid] += smk[tid + s]; }
        __syncthreads();
    }
    if (tid == 0) {
        float vl = smk[0] < 1.f ? 1.f : smk[0];
        out[b] = sp[0] / sqrtf(vl);
    }
}

// ---------------------------------------------------------------------------
// Launch
// ---------------------------------------------------------------------------
extern "C" void kernel_launch(void* const* d_in, const int* in_sizes, int n_in,
                              void* d_out, int out_size) {
    const float* h_V  = (const float*)d_in[0];
    const float* h_E  = (const float*)d_in[1];
    const float* mask = (const float*)d_in[2];
    const float* fw1  = (const float*)d_in[3];
    const float* fb1  = (const float*)d_in[4];
    const float* fw2  = (const float*)d_in[5];
    const float* fb2  = (const float*)d_in[6];
    const float* hw1  = (const float*)d_in[7];
    const float* hb1  = (const float*)d_in[8];
    const float* hw2  = (const float*)d_in[9];
    const float* hb2  = (const float*)d_in[10];
    const float* hw3  = (const float*)d_in[11];
    const float* hb3  = (const float*)d_in[12];
    float* out = (float*)d_out;

    static int configured = 0;
    if (!configured) {
        cudaFuncSetAttribute(gemm1_mma, cudaFuncAttributeMaxDynamicSharedMemorySize, SMEM1);
        cudaFuncSetAttribute(gemm2_mma, cudaFuncAttributeMaxDynamicSharedMemorySize, SMEM2);
        configured = 1;
    }

    conv_hE<<<((size_t)M1_ * H_) / (256 * 4), 256>>>(h_E);
    transpose_w<<<(F_ * H_ + F_ * F_ + 255) / 256, 256>>>(fw1, fw2);

    dim3 g1(F_ / 128, M1_ / 128);            // (3, 4608)
    gemm1_mma<<<g1, 256, SMEM1>>>(fb1);

    dim3 g2(F_ / 128, B_ * L_);              // (3, 1536)
    gemm2_mma<<<g2, 256, SMEM2>>>(h_V, fb2);

    head_kernel<<<B_ * L_, 128>>>(hw1, hb1, hw2, hb2, hw3, hb3, mask);
    reduce_kernel<<<B_, 128>>>(mask, out);
}